// round 1
// baseline (speedup 1.0000x reference)
#include <cuda_runtime.h>
#include <cuda_bf16.h>
#include <cstdint>

#define EPSF 1e-8f
static constexpr int B_  = 8;
static constexpr int N_  = 256;
static constexpr int NF_ = 2048;

// Scratch: K matrices, bf16, [B,N,N] = 1 MB (L2-resident between kernels)
__device__ __nv_bfloat16 g_K[B_ * N_ * N_];

// ---------------------------------------------------------------------------
// Kernel 1: block-mean pooling (8x8) of A_full row-block -> one row of A_lat,
// then row-normalize + K = (W+EPS)^10 (== exp(-C/EPS_OT)), store bf16.
// Grid: (256, 8) = (row-block I, batch b), 256 threads.
// ---------------------------------------------------------------------------
__global__ void __launch_bounds__(256) pool_build_k(const float* __restrict__ A)
{
    const int I = blockIdx.x, b = blockIdx.y;
    const int t = threadIdx.x;
    const float* base = A + ((size_t)b * NF_ + (size_t)I * 8) * NF_;

    float4 a0 = make_float4(0.f, 0.f, 0.f, 0.f);
    float4 a1 = make_float4(0.f, 0.f, 0.f, 0.f);
#pragma unroll
    for (int r = 0; r < 8; ++r) {
        const float4* row = reinterpret_cast<const float4*>(base + (size_t)r * NF_);
        float4 f0 = __ldcs(row + t);
        float4 f1 = __ldcs(row + t + 256);
        a0.x += f0.x; a0.y += f0.y; a0.z += f0.z; a0.w += f0.w;
        a1.x += f1.x; a1.y += f1.y; a1.z += f1.z; a1.w += f1.w;
    }
    float s0 = (a0.x + a0.y) + (a0.z + a0.w);
    float s1 = (a1.x + a1.y) + (a1.z + a1.w);
    // pair-combine: block J covers 8 consecutive columns = two threads' float4s
    s0 += __shfl_xor_sync(0xffffffffu, s0, 1);
    s1 += __shfl_xor_sync(0xffffffffu, s1, 1);

    __shared__ float srow[256];
    __shared__ float red[9];
    if ((t & 1) == 0) {
        srow[(t >> 1)]       = s0 * (1.0f / 64.0f);
        srow[128 + (t >> 1)] = s1 * (1.0f / 64.0f);
    }
    __syncthreads();

    float w = srow[t];
    w = w > 0.0f ? w : 0.0f;            // relu
    // block reduce: row sum
    float rv = w;
#pragma unroll
    for (int o = 16; o; o >>= 1) rv += __shfl_xor_sync(0xffffffffu, rv, o);
    if ((t & 31) == 0) red[t >> 5] = rv;
    __syncthreads();
    if (t == 0) {
        float s = 0.f;
#pragma unroll
        for (int i = 0; i < 8; ++i) s += red[i];
        red[8] = s;
    }
    __syncthreads();
    float rowsum = red[8];

    float W = (rowsum > EPSF) ? (w / (rowsum + EPSF)) : (1.0f / 256.0f);
    float x  = W + EPSF;
    float x2 = x * x, x4 = x2 * x2, x8 = x4 * x4;
    g_K[((size_t)b * N_ + I) * N_ + t] = __float2bfloat16(x8 * x2);  // x^10
}

// ---------------------------------------------------------------------------
// Kernel 2 helpers
// ---------------------------------------------------------------------------
__device__ __forceinline__ void unpack8(uint4 kr, float* f)
{
    float2 f0 = __bfloat1622float2(*reinterpret_cast<__nv_bfloat162*>(&kr.x));
    float2 f1 = __bfloat1622float2(*reinterpret_cast<__nv_bfloat162*>(&kr.y));
    float2 f2 = __bfloat1622float2(*reinterpret_cast<__nv_bfloat162*>(&kr.z));
    float2 f3 = __bfloat1622float2(*reinterpret_cast<__nv_bfloat162*>(&kr.w));
    f[0] = f0.x; f[1] = f0.y; f[2] = f1.x; f[3] = f1.y;
    f[4] = f2.x; f[5] = f2.y; f[6] = f3.x; f[7] = f3.y;
}

__device__ __forceinline__ float dot8(uint4 kr, const float* vj)
{
    float kf[8];
    unpack8(kr, kf);
    float acc = 0.f;
#pragma unroll
    for (int x = 0; x < 8; ++x) acc = fmaf(kf[x], vj[x], acc);
    return acc;
}

__device__ __forceinline__ float blk_sum(float v, float* red)
{
#pragma unroll
    for (int o = 16; o; o >>= 1) v += __shfl_xor_sync(0xffffffffu, v, o);
    if ((threadIdx.x & 31) == 0) red[threadIdx.x >> 5] = v;
    __syncthreads();
    if (threadIdx.x == 0) {
        float s = 0.f;
        const int nw = blockDim.x >> 5;
        for (int i = 0; i < nw; ++i) s += red[i];
        red[32] = s;
    }
    __syncthreads();
    float r = red[32];
    __syncthreads();
    return r;
}

__device__ __forceinline__ float blk_max(float v, float* red)
{
#pragma unroll
    for (int o = 16; o; o >>= 1) v = fmaxf(v, __shfl_xor_sync(0xffffffffu, v, o));
    if ((threadIdx.x & 31) == 0) red[threadIdx.x >> 5] = v;
    __syncthreads();
    if (threadIdx.x == 0) {
        float s = -3.4e38f;
        const int nw = blockDim.x >> 5;
        for (int i = 0; i < nw; ++i) s = fmaxf(s, red[i]);
        red[32] = s;
    }
    __syncthreads();
    float r = red[32];
    __syncthreads();
    return r;
}

// ---------------------------------------------------------------------------
// Kernel 2: per-batch Sinkhorn + Kuramoto. One CTA per batch, 1024 threads.
// K lives in shared memory (bf16, 128KB). Fixed-point early exit on (u,v).
// ---------------------------------------------------------------------------
__global__ void __launch_bounds__(1024, 1) solve_kernel(
    const float* __restrict__ theta_g, const float* __restrict__ gamma_g,
    const float* __restrict__ omega_g, const float* __restrict__ alpha_g,
    const float* __restrict__ logk_g,  float* __restrict__ out)
{
    extern __shared__ char sm[];
    __nv_bfloat16* Ks = reinterpret_cast<__nv_bfloat16*>(sm);         // 131072 B
    float* part  = reinterpret_cast<float*>(sm + 131072);             // 2048 f
    float* theta = part + 2048;                                       // 256 f
    float* gam   = theta + 256;
    float* p     = gam + 256;
    float* u     = p + 256;
    float* v     = u + 256;
    float* Kv    = v + 256;
    float* red   = Kv + 256;                                          // 33 f
    int*   flg   = reinterpret_cast<int*>(red + 34);

    const int b    = blockIdx.x;
    const int t    = threadIdx.x;
    const int wid  = t >> 5;
    const int lane = t & 31;

    // ---- load K tile into smem (131072 B = 8192 uint4) ----
    {
        const uint4* gk = reinterpret_cast<const uint4*>(g_K + (size_t)b * N_ * N_);
        uint4* sk = reinterpret_cast<uint4*>(Ks);
#pragma unroll
        for (int i = 0; i < 8; ++i) sk[t + 1024 * i] = gk[t + 1024 * i];
    }
    if (t < 256) {
        theta[t] = theta_g[b * N_ + t];
        gam[t]   = gamma_g[b * N_ + t];
    }
    if (t == 0) flg[0] = 0;
    __syncthreads();

    // ---- p = softmax(gamma) ----
    {
        float val = (t < 256) ? gam[t] : -3.4e38f;
        float m = blk_max(val, red);
        float e = (t < 256) ? expf(gam[t] - m) : 0.f;
        float s = blk_sum(e, red);
        if (t < 256) {
            p[t] = e / s;
            u[t] = 1.0f / 256.0f;
            v[t] = 1.0f / 256.0f;
        }
    }
    __syncthreads();

    // ---- Sinkhorn iterations (with exact fixed-point early exit) ----
    for (int it = 0; it < 10; ++it) {
        float uo = 0.f, vo = 0.f;
        if (t < 256) { uo = u[t]; vo = v[t]; }

        // Kv[i] = sum_j K[i][j] v[j]; u[i] = p[i] / (Kv[i]+EPS)
        {
            float vj[8];
#pragma unroll
            for (int x = 0; x < 8; ++x) vj[x] = v[lane * 8 + x];
#pragma unroll
            for (int k = 0; k < 8; ++k) {
                int i = wid * 8 + k;
                uint4 kr = reinterpret_cast<const uint4*>(Ks + i * N_)[lane];
                float acc = dot8(kr, vj);
#pragma unroll
                for (int o = 16; o; o >>= 1) acc += __shfl_xor_sync(0xffffffffu, acc, o);
                if (lane == 0) u[i] = p[i] / (acc + EPSF);
            }
        }
        __syncthreads();

        // KTu[j] = sum_i K[i][j] u[i] (8 row-group partials)
        {
            const int g  = t >> 7;           // 0..7
            const int j0 = (t & 127) * 2;    // column pair
            float ax = 0.f, ay = 0.f;
#pragma unroll
            for (int k = 0; k < 32; ++k) {
                int i = g * 32 + k;
                __nv_bfloat162 kk = *reinterpret_cast<const __nv_bfloat162*>(Ks + i * N_ + j0);
                float2 f = __bfloat1622float2(kk);
                float ui = u[i];
                ax = fmaf(f.x, ui, ax);
                ay = fmaf(f.y, ui, ay);
            }
            *reinterpret_cast<float2*>(&part[g * N_ + j0]) = make_float2(ax, ay);
        }
        __syncthreads();
        if (t < 256) {
            float s = 0.f;
#pragma unroll
            for (int g = 0; g < 8; ++g) s += part[g * N_ + t];
            float nv = (1.0f / 256.0f) / (s + EPSF);
            v[t] = nv;
            if (nv != vo || u[t] != uo) flg[0] = 1;   // any bitwise change?
        }
        __syncthreads();
        int changed = flg[0];
        __syncthreads();
        if (t == 0) flg[0] = 0;
        if (!changed) break;   // (u,v) fixed point: all remaining iters identical
    }
    __syncthreads();

    // ---- final Kv with converged v, then S = sum_ij u K v ----
    {
        float vj[8];
#pragma unroll
        for (int x = 0; x < 8; ++x) vj[x] = v[lane * 8 + x];
#pragma unroll
        for (int k = 0; k < 8; ++k) {
            int i = wid * 8 + k;
            uint4 kr = reinterpret_cast<const uint4*>(Ks + i * N_)[lane];
            float acc = dot8(kr, vj);
#pragma unroll
            for (int o = 16; o; o >>= 1) acc += __shfl_xor_sync(0xffffffffu, acc, o);
            if (lane == 0) Kv[i] = acc;
        }
    }
    __syncthreads();
    float sv = (t < 256) ? u[t] * Kv[t] : 0.f;
    float S = blk_sum(sv, red);
    float Sinv = 1.0f / (S + EPSF);

    // ---- Kuramoto coupling + output ----
    {
        float vj[8], tj[8];
#pragma unroll
        for (int x = 0; x < 8; ++x) {
            vj[x] = v[lane * 8 + x];
            tj[x] = theta[lane * 8 + x];
        }
        const float4* a4 = reinterpret_cast<const float4*>(alpha_g);
#pragma unroll
        for (int k = 0; k < 8; ++k) {
            int i = wid * 8 + k;
            float ti = theta[i];
            uint4 kr = reinterpret_cast<const uint4*>(Ks + i * N_)[lane];
            float kf[8];
            unpack8(kr, kf);
            float4 al0 = __ldg(a4 + i * 64 + lane * 2);
            float4 al1 = __ldg(a4 + i * 64 + lane * 2 + 1);
            float al[8] = {al0.x, al0.y, al0.z, al0.w, al1.x, al1.y, al1.z, al1.w};
            float acc = 0.f;
#pragma unroll
            for (int x = 0; x < 8; ++x) {
                float d = tj[x] - ti - al[x];
                acc = fmaf(kf[x] * vj[x], __sinf(d), acc);
            }
#pragma unroll
            for (int o = 16; o; o >>= 1) acc += __shfl_xor_sync(0xffffffffu, acc, o);
            if (lane == 0) {
                float coup = u[i] * Sinv * acc;               // K_COUP = 1
                float kap  = log1pf(expf(logk_g[i]));         // softplus
                float td   = omega_g[i] + coup + kap * (gam[i] - ti);
                out[b * N_ + i] = ti + td;                    // DT = 1
            }
        }
    }
}

// ---------------------------------------------------------------------------
extern "C" void kernel_launch(void* const* d_in, const int* in_sizes, int n_in,
                              void* d_out, int out_size)
{
    const float* theta = (const float*)d_in[0];
    const float* gamma = (const float*)d_in[1];
    const float* A     = (const float*)d_in[2];
    const float* omega = (const float*)d_in[3];
    const float* alpha = (const float*)d_in[4];
    const float* logk  = (const float*)d_in[5];
    float* out = (float*)d_out;

    dim3 g1(256, 8);
    pool_build_k<<<g1, 256>>>(A);

    const int smem = 131072 + 2048 * 4 + 6 * 256 * 4 + 34 * 4 + 16;
    cudaFuncSetAttribute(solve_kernel, cudaFuncAttributeMaxDynamicSharedMemorySize, smem);
    solve_kernel<<<B_, 1024, smem>>>(theta, gamma, omega, alpha, logk, out);
}